// round 1
// baseline (speedup 1.0000x reference)
#include <cuda_runtime.h>
#include <cstdint>

// Problem constants (fixed by setup_inputs)
#define BB 4
#define CC 64
#define HH 192
#define WW 192
#define HWW (HH*WW)
#define DG 8
#define CG 8          // CC / DG
#define KK 9
#define NPIX (BB*HWW) // 147456

#define TW 32
#define TH 8
#define NTHR 256
#define CIN_CHUNK 8

// ---------------- scratch (static device globals; no allocs) ----------------
__device__ float g_buf1[(size_t)CC * NPIX];
__device__ float g_buf2[(size_t)CC * NPIX];
__device__ float g_buf3[(size_t)CC * NPIX];
__device__ float g_buf4[(size_t)CC * NPIX];
__device__ float g_off [(size_t)216 * NPIX];
__device__ float g_xt  [(size_t)CC * NPIX];   // x transposed to (B, DG, H, W, CG)

// ---------------- direct 3x3 conv, stride 1, pad 1 ----------------
// in0: (B, C0, H, W). in1 (optional): (B, Cin-C0, H, W) -> logical cat on channel dim.
// wgt: (Cout, Cin, 3, 3), bias: (Cout).
// Each block computes a TWxTH pixel tile for OCB output channels (gridDim.z = B * Cout/OCB).
template<int OCB, bool LRELU>
__global__ __launch_bounds__(NTHR, 2)
void conv3x3_kernel(const float* __restrict__ in0,
                    const float* __restrict__ in1, int C0, int Cin,
                    const float* __restrict__ wgt,
                    const float* __restrict__ bias,
                    float* __restrict__ out, int Cout)
{
    __shared__ __align__(16) float sIn[CIN_CHUNK][TH + 2][TW + 2];
    __shared__ __align__(16) float sW[CIN_CHUNK * 9 * OCB];

    const int nOcb  = Cout / OCB;
    const int b     = blockIdx.z / nOcb;
    const int ocb   = blockIdx.z % nOcb;
    const int ocBase = ocb * OCB;

    const int tid = threadIdx.x;
    const int tx  = tid % TW;
    const int ty  = tid / TW;

    const int gx0 = blockIdx.x * TW - 1;
    const int gy0 = blockIdx.y * TH - 1;

    float acc[OCB];
#pragma unroll
    for (int i = 0; i < OCB; ++i) acc[i] = 0.f;

    for (int cb = 0; cb < Cin; cb += CIN_CHUNK) {
        __syncthreads();
        // load input tile (halo'd) for CIN_CHUNK channels
        for (int i = tid; i < CIN_CHUNK * (TH + 2) * (TW + 2); i += NTHR) {
            int col = i % (TW + 2);
            int r2  = i / (TW + 2);
            int row = r2 % (TH + 2);
            int ci  = r2 / (TH + 2);
            int gy = gy0 + row, gx = gx0 + col;
            int c  = cb + ci;
            float v = 0.f;
            if (gy >= 0 && gy < HH && gx >= 0 && gx < WW) {
                const float* src = (c < C0)
                    ? in0 + ((size_t)(b * C0 + c)) * HWW
                    : in1 + ((size_t)(b * (Cin - C0) + (c - C0))) * HWW;
                v = src[gy * WW + gx];
            }
            sIn[ci][row][col] = v;
        }
        // load weights for this cin chunk: sW[(ci*9+k)*OCB + oc]
        for (int i = tid; i < CIN_CHUNK * 9 * OCB; i += NTHR) {
            int oc = i % OCB;
            int r  = i / OCB;
            int k  = r % 9;
            int ci = r / 9;
            sW[i] = wgt[(size_t)(ocBase + oc) * (Cin * 9) + (cb + ci) * 9 + k];
        }
        __syncthreads();

        for (int ci = 0; ci < CIN_CHUNK; ++ci) {
            float v[9];
#pragma unroll
            for (int kh = 0; kh < 3; ++kh)
#pragma unroll
                for (int kw = 0; kw < 3; ++kw)
                    v[kh * 3 + kw] = sIn[ci][ty + kh][tx + kw];

            const float4* wrow = reinterpret_cast<const float4*>(&sW[ci * 9 * OCB]);
#pragma unroll
            for (int k = 0; k < 9; ++k) {
#pragma unroll
                for (int o4 = 0; o4 < OCB / 4; ++o4) {
                    float4 w = wrow[k * (OCB / 4) + o4];
                    acc[o4 * 4 + 0] += w.x * v[k];
                    acc[o4 * 4 + 1] += w.y * v[k];
                    acc[o4 * 4 + 2] += w.z * v[k];
                    acc[o4 * 4 + 3] += w.w * v[k];
                }
            }
        }
    }

    const int gy = blockIdx.y * TH + ty;
    const int gx = blockIdx.x * TW + tx;
#pragma unroll
    for (int oc = 0; oc < OCB; ++oc) {
        float r = acc[oc] + __ldg(&bias[ocBase + oc]);
        if (LRELU) r = (r >= 0.f) ? r : 0.1f * r;
        out[((size_t)(b * Cout + ocBase + oc)) * HWW + gy * WW + gx] = r;
    }
}

// ---------------- transpose x: (B,64,H,W) -> (B,DG,H,W,CG) ----------------
__global__ void transpose_kernel(const float* __restrict__ in, float* __restrict__ out)
{
    int idx = blockIdx.x * blockDim.x + threadIdx.x;   // over B*DG*H*W
    if (idx >= BB * DG * HWW) return;
    int x = idx % WW;
    int r = idx / WW;
    int y = r % HH; r /= HH;
    int dg = r % DG;
    int b  = r / DG;
    const float* src = in + ((size_t)(b * CC + dg * CG)) * HWW + y * WW + x;
    float4 v0, v1;
    v0.x = src[0 * HWW]; v0.y = src[1 * HWW]; v0.z = src[2 * HWW]; v0.w = src[3 * HWW];
    v1.x = src[4 * HWW]; v1.y = src[5 * HWW]; v1.z = src[6 * HWW]; v1.w = src[7 * HWW];
    float4* dst = reinterpret_cast<float4*>(out + (size_t)idx * 8);
    dst[0] = v0; dst[1] = v1;
}

// ---------------- modulated deformable conv (DCNv2) ----------------
// xt:  (B, DG, H, W, CG) channel-last-transposed input
// off: (B, 216, H, W) raw conv output; ch [0,144)=offsets (dg*18+2k+{y,x}), [144,216)=mask logits
// wgt: (64, 64, 3, 3) -> w[o][dg*8+cg][kh][kw]
template<bool LRELU>
__global__ __launch_bounds__(NTHR, 2)
void dcn_kernel(const float* __restrict__ xt,
                const float* __restrict__ off,
                const float* __restrict__ wgt,
                const float* __restrict__ bias,
                float* __restrict__ out)
{
    __shared__ __align__(16) float sW[CG * 9 * 64];   // [(cg*9+k)*64 + oc]

    const int tid = threadIdx.x;
    const int tx  = tid % TW;
    const int ty  = tid / TW;
    const int b   = blockIdx.z;
    const int gx  = blockIdx.x * TW + tx;
    const int gy  = blockIdx.y * TH + ty;

    float acc[64];
#pragma unroll
    for (int i = 0; i < 64; ++i) acc[i] = 0.f;

    const float* offB = off + (size_t)b * 216 * HWW + gy * WW + gx;

    for (int dg = 0; dg < DG; ++dg) {
        __syncthreads();
        for (int i = tid; i < CG * 9 * 64; i += NTHR) {
            int oc = i % 64;
            int r  = i / 64;
            int k  = r % 9;
            int cg = r / 9;
            sW[i] = wgt[(size_t)oc * (CC * 9) + (dg * CG + cg) * 9 + k];
        }
        __syncthreads();

        const float* xdg = xt + ((size_t)(b * DG + dg)) * HWW * CG;

        for (int k = 0; k < 9; ++k) {
            float dy = offB[(size_t)(dg * 18 + 2 * k + 0) * HWW];
            float dx = offB[(size_t)(dg * 18 + 2 * k + 1) * HWW];
            float ml = offB[(size_t)(144 + dg * 9 + k) * HWW];
            float m  = 1.f / (1.f + __expf(-ml));

            float py = (float)gy - 1.f + (float)(k / 3) + dy;
            float px = (float)gx - 1.f + (float)(k % 3) + dx;
            float y0f = floorf(py), x0f = floorf(px);
            float wy = py - y0f, wx = px - x0f;
            int y0 = (int)y0f, x0 = (int)x0f;

            float cw00 = (1.f - wy) * (1.f - wx);
            float cw01 = (1.f - wy) * wx;
            float cw10 = wy * (1.f - wx);
            float cw11 = wy * wx;

            float sv[8];
#pragma unroll
            for (int i = 0; i < 8; ++i) sv[i] = 0.f;

#pragma unroll
            for (int cy = 0; cy < 2; ++cy) {
#pragma unroll
                for (int cx = 0; cx < 2; ++cx) {
                    int yy = y0 + cy, xx = x0 + cx;
                    float cwv = (cy == 0) ? ((cx == 0) ? cw00 : cw01)
                                          : ((cx == 0) ? cw10 : cw11);
                    if (yy >= 0 && yy < HH && xx >= 0 && xx < WW) {
                        const float4* p = reinterpret_cast<const float4*>(
                            xdg + ((size_t)yy * WW + xx) * CG);
                        float4 a = __ldg(&p[0]);
                        float4 c = __ldg(&p[1]);
                        sv[0] += cwv * a.x; sv[1] += cwv * a.y;
                        sv[2] += cwv * a.z; sv[3] += cwv * a.w;
                        sv[4] += cwv * c.x; sv[5] += cwv * c.y;
                        sv[6] += cwv * c.z; sv[7] += cwv * c.w;
                    }
                }
            }

#pragma unroll
            for (int cg = 0; cg < CG; ++cg) {
                float s = sv[cg] * m;
                const float4* wr = reinterpret_cast<const float4*>(&sW[(cg * 9 + k) * 64]);
#pragma unroll
                for (int o4 = 0; o4 < 16; ++o4) {
                    float4 w = wr[o4];
                    acc[o4 * 4 + 0] += w.x * s;
                    acc[o4 * 4 + 1] += w.y * s;
                    acc[o4 * 4 + 2] += w.z * s;
                    acc[o4 * 4 + 3] += w.w * s;
                }
            }
        }
    }

#pragma unroll
    for (int oc = 0; oc < 64; ++oc) {
        float r = acc[oc] + __ldg(&bias[oc]);
        if (LRELU) r = (r >= 0.f) ? r : 0.1f * r;
        out[((size_t)(b * CC + oc)) * HWW + gy * WW + gx] = r;
    }
}

// ---------------- launch ----------------
extern "C" void kernel_launch(void* const* d_in, const int* in_sizes, int n_in,
                              void* d_out, int out_size)
{
    const float* nbr     = (const float*)d_in[0];
    const float* ref     = (const float*)d_in[1];
    const float* oc1_w   = (const float*)d_in[2];
    const float* oc1_b   = (const float*)d_in[3];
    const float* oc2_w   = (const float*)d_in[4];
    const float* oc2_b   = (const float*)d_in[5];
    const float* d1off_w = (const float*)d_in[6];
    const float* d1off_b = (const float*)d_in[7];
    const float* dcn1_w  = (const float*)d_in[8];
    const float* dcn1_b  = (const float*)d_in[9];
    const float* fc_w    = (const float*)d_in[10];
    const float* fc_b    = (const float*)d_in[11];
    const float* cas1_w  = (const float*)d_in[12];
    const float* cas1_b  = (const float*)d_in[13];
    const float* cas2_w  = (const float*)d_in[14];
    const float* cas2_b  = (const float*)d_in[15];
    const float* cdoff_w = (const float*)d_in[16];
    const float* cdoff_b = (const float*)d_in[17];
    const float* casd_w  = (const float*)d_in[18];
    const float* casd_b  = (const float*)d_in[19];
    float* outp = (float*)d_out;

    float *buf1, *buf2, *buf3, *buf4, *offb, *xt;
    cudaGetSymbolAddress((void**)&buf1, g_buf1);
    cudaGetSymbolAddress((void**)&buf2, g_buf2);
    cudaGetSymbolAddress((void**)&buf3, g_buf3);
    cudaGetSymbolAddress((void**)&buf4, g_buf4);
    cudaGetSymbolAddress((void**)&offb, g_off);
    cudaGetSymbolAddress((void**)&xt,   g_xt);

    dim3 gC(WW / TW, HH / TH, BB);         // 64-out convs / dcn
    dim3 gO(WW / TW, HH / TH, BB * 3);     // 216-out convs (3 blocks of 72)
    int tpGrid = (BB * DG * HWW + NTHR - 1) / NTHR;

    // 1) offset = lrelu(conv(cat(nbr, ref), oc1))
    conv3x3_kernel<64, true ><<<gC, NTHR>>>(nbr, ref, CC, 2 * CC, oc1_w, oc1_b, buf1, 64);
    // 2) offset = lrelu(conv(offset, oc2))
    conv3x3_kernel<64, true ><<<gC, NTHR>>>(buf1, nullptr, CC, CC, oc2_w, oc2_b, buf2, 64);
    // 3) dcn1 offset/mask conv (216 ch, raw)
    conv3x3_kernel<72, false><<<gO, NTHR>>>(buf2, nullptr, CC, CC, d1off_w, d1off_b, offb, 216);
    // 4) transpose nbr for gathers
    transpose_kernel<<<tpGrid, NTHR>>>(nbr, xt);
    // 5) feat = dcn(nbr, off)
    dcn_kernel<false><<<gC, NTHR>>>(xt, offb, dcn1_w, dcn1_b, buf3);
    // 6) feat = conv(feat, fc)
    conv3x3_kernel<64, false><<<gC, NTHR>>>(buf3, nullptr, CC, CC, fc_w, fc_b, buf4, 64);
    // 7) offset = lrelu(conv(cat(feat, ref), cas1))
    conv3x3_kernel<64, true ><<<gC, NTHR>>>(buf4, ref, CC, 2 * CC, cas1_w, cas1_b, buf1, 64);
    // 8) offset = lrelu(conv(offset, cas2))
    conv3x3_kernel<64, true ><<<gC, NTHR>>>(buf1, nullptr, CC, CC, cas2_w, cas2_b, buf2, 64);
    // 9) casd offset/mask conv
    conv3x3_kernel<72, false><<<gO, NTHR>>>(buf2, nullptr, CC, CC, cdoff_w, cdoff_b, offb, 216);
    // 10) transpose feat
    transpose_kernel<<<tpGrid, NTHR>>>(buf4, xt);
    // 11) out = lrelu(dcn(feat, off))
    dcn_kernel<true><<<gC, NTHR>>>(xt, offb, casd_w, casd_b, outp);

    (void)in_sizes; (void)n_in; (void)out_size;
}